// round 12
// baseline (speedup 1.0000x reference)
#include <cuda_runtime.h>
#include <cstdint>
#include <math.h>

// ---------------- problem constants ----------------
#define BDIM 256
#define DIN 2048
#define HID 2048
#define DCTX 1024
#define NSEG 10
#define NR (HID * NSEG) /* 20480 */
#define OUTD 100
#define KWIN 102

#define DW 128    // ELL row width for dendrite rows (mean nz 51.2)
#define FW 192    // ELL width for FF rows (mean nz 102.4)

typedef unsigned long long u64;

// ---------------- scratch (no allocations allowed) ----------------
__device__ float g_ctxT[DCTX * BDIM];       // 1 MB  context transposed [c][b]
__device__ float g_xT[DIN * BDIM];          // 2 MB  x transposed [c][b]
__device__ float g_hT[HID * BDIM];          // 2 MB  layer-1 winners transposed [c][b]
__device__ float g_yT[HID * BDIM];          // 2 MB  ff pre-activation [n][b]
__device__ float g_gT1[HID * BDIM];         // 2 MB  dendrite gate layer 1 [u][b]
__device__ float g_gT2[HID * BDIM];         // 2 MB  dendrite gate layer 2 [u][b]
__device__ float g_h2[BDIM * HID];          // 2 MB  layer-2 winners, row-major
__device__ __align__(16) u64 g_ellD1[(size_t)NR * DW];   // 21 MB ELL (dendrite L1)
__device__ __align__(16) u64 g_ellD2[(size_t)NR * DW];   // 21 MB ELL (dendrite L2)
__device__ int  g_cntD1[NR];
__device__ int  g_cntD2[NR];
__device__ __align__(16) u64 g_ellF1[(size_t)HID * FW];  // 3 MB  ELL (ff L1)
__device__ __align__(16) u64 g_ellF2[(size_t)HID * FW];  // 3 MB  ELL (ff L2)
__device__ int  g_cntF1[HID];
__device__ int  g_cntF2[HID];

// =====================================================================
// warp-per-row ELL compaction. NEW: ballot+popc positioning (no 5-deep
// shfl scan). Lane-major ascending column order preserved exactly:
// cross-lane offset from masked ballots, in-lane order from p++.
// entry = (f32 weight bits << 32) | (col * mult).
// =====================================================================
__device__ __forceinline__
void build_row(const float* __restrict__ W, const float* __restrict__ M,
               u64* __restrict__ ell, int* __restrict__ cnt,
               int K, int width, int mult, int row, int lane) {
    const float4* wr = (const float4*)(W + (size_t)row * K);
    const float4* mr = (const float4*)(M + (size_t)row * K);
    u64* er = ell + (size_t)row * width;
    const int chunks = K >> 7;  // 128 floats per chunk (float4 per lane)
    const unsigned below = (1u << lane) - 1u;
    int base = 0;
    float4 w = wr[lane];
    float4 m = mr[lane];
    for (int c = 0; c < chunks; ++c) {
        float4 wn, mn;
        if (c + 1 < chunks) {
            wn = wr[(c + 1) * 32 + lane];
            mn = mr[(c + 1) * 32 + lane];
        }
        const unsigned bx = __ballot_sync(0xffffffffu, m.x != 0.f);
        const unsigned by = __ballot_sync(0xffffffffu, m.y != 0.f);
        const unsigned bz = __ballot_sync(0xffffffffu, m.z != 0.f);
        const unsigned bw = __ballot_sync(0xffffffffu, m.w != 0.f);
        int p = base + __popc(bx & below) + __popc(by & below)
                     + __popc(bz & below) + __popc(bw & below);
        const int col0 = c * 128 + lane * 4;
        if (m.x != 0.f && p < width) er[p++] = ((u64)__float_as_uint(w.x) << 32) | (unsigned)((col0 + 0) * mult);
        if (m.y != 0.f && p < width) er[p++] = ((u64)__float_as_uint(w.y) << 32) | (unsigned)((col0 + 1) * mult);
        if (m.z != 0.f && p < width) er[p++] = ((u64)__float_as_uint(w.z) << 32) | (unsigned)((col0 + 2) * mult);
        if (m.w != 0.f && p < width) er[p++] = ((u64)__float_as_uint(w.w) << 32) | (unsigned)((col0 + 3) * mult);
        base += __popc(bx) + __popc(by) + __popc(bz) + __popc(bw);
        w = wn; m = mn;
    }
    if (lane == 0) cnt[row] = base < width ? base : width;
}

// =====================================================================
// K1a: fused builds only.
// Block ranges:
//   [0,2560)      build dendrite L1   (8 rows/block, /2560 %2560 decode)
//   [2560,5120)   build dendrite L2
//   [5120,5376)   build FF L1
//   [5376,5632)   build FF L2
// =====================================================================
__global__ __launch_bounds__(256)
void prep_build(const float* __restrict__ segW1, const float* __restrict__ maskS1,
                const float* __restrict__ segW2, const float* __restrict__ maskS2,
                const float* __restrict__ W1, const float* __restrict__ maskW1,
                const float* __restrict__ W2, const float* __restrict__ maskW2) {
    const int bid = blockIdx.x;
    const int tid = threadIdx.x;
    const int lane = tid & 31;
    const int wid = tid >> 5;

    if (bid < 5120) {  // dendrite builds
        const int part = bid / 2560;                 // 0 or 1
        const int row = (bid % 2560) * 8 + wid;      // 0..20479
        if (part == 0) build_row(segW1, maskS1, g_ellD1, g_cntD1, DCTX, DW, 128, row, lane);
        else           build_row(segW2, maskS2, g_ellD2, g_cntD2, DCTX, DW, 128, row, lane);
        return;
    }
    // FF builds
    const int part = (bid - 5120) >> 8;              // 0 or 1 (256 blocks each)
    const int row = ((bid - 5120) & 255) * 8 + wid;
    if (part == 0) build_row(W1, maskW1, g_ellF1, g_cntF1, DIN, FW, 1024, row, lane);
    else           build_row(W2, maskW2, g_ellF2, g_cntF2, HID, FW, 1024, row, lane);
}

// =====================================================================
// K1b: both transposes. Block ranges: [0,256) ctx, [256,768) x.
// in[R=256][C] -> out[C][256]
// =====================================================================
__global__ __launch_bounds__(256)
void prep_transpose(const float* __restrict__ ctx, const float* __restrict__ x) {
    __shared__ float t[32][33];
    const int bid = blockIdx.x;
    const int tid = threadIdx.x;
    const float* in;
    float* outp;
    int C, lb;
    if (bid < 256) { in = ctx; outp = g_ctxT; C = DCTX; lb = bid; }
    else           { in = x;   outp = g_xT;   C = DIN;  lb = bid - 256; }
    const int nbx = C >> 5;
    const int c0 = (lb % nbx) * 32;
    const int r0 = (lb / nbx) * 32;
    const int xx = tid & 31, yy = tid >> 5;
#pragma unroll
    for (int i = 0; i < 32; i += 8)
        t[yy + i][xx] = in[(size_t)(r0 + yy + i) * C + c0 + xx];
    __syncthreads();
#pragma unroll
    for (int i = 0; i < 32; i += 8)
        outp[(size_t)(c0 + yy + i) * BDIM + r0 + xx] = t[xx][yy + i];
}

// =====================================================================
// K2: fused dendrite spMM + gate for BOTH layers.
// NEW: entry loads vectorized to LDG.128 (ulonglong2) — halves the
// broadcast-LDG wavefront count. Same unroll-4, same FP order.
// 1024 threads, smem = 32-batch ctx tile (128 KB).
// grid 256: [layer(2)][by(8)][bx(16)].   <-- PROFILED (user slot 4)
// =====================================================================
__global__ __launch_bounds__(1024, 1)
void dspmm_gate2(const float* __restrict__ ctxT) {
    extern __shared__ float s[];  // DCTX * 32 floats = 128 KB
    const int id = blockIdx.x;
    const int layer = id >> 7;
    const int bx = id & 15;
    const int by = (id & 127) >> 4;
    const u64* __restrict__ ell = layer ? g_ellD2 : g_ellD1;
    const int* __restrict__ cnt = layer ? g_cntD2 : g_cntD1;
    float* __restrict__ gT = layer ? g_gT2 : g_gT1;

    const int b0 = by * 32;
    const int tid = threadIdx.x;
    for (int i = tid; i < DCTX * 8; i += 1024) {
        const int c = i >> 3, q = (i & 7) * 4;
        *(float4*)&s[c * 32 + q] =
            *(const float4*)&ctxT[(size_t)c * 256 + b0 + q];
    }
    __syncthreads();
    const int wid = tid >> 5, lane = tid & 31;
    const char* sb = (const char*)s + lane * 4;

#pragma unroll
    for (int i = 0; i < 4; ++i) {
        const int u = bx * 128 + wid * 4 + i;
        const int r0 = u * NSEG;
        int cn = (lane < NSEG) ? cnt[r0 + lane] : 0;
        if (cn > DW) cn = DW;
        float accs[NSEG];
#pragma unroll
        for (int sg = 0; sg < NSEG; ++sg) {
            const int n = __shfl_sync(0xffffffffu, cn, sg);
            const u64* e = ell + (size_t)(r0 + sg) * DW;
            const ulonglong2* e2 = (const ulonglong2*)e;
            float acc = 0.f;
            int j = 0;
            for (; j + 4 <= n; j += 4) {
                const ulonglong2 p0 = e2[(j >> 1)];
                const ulonglong2 p1 = e2[(j >> 1) + 1];
                acc += __uint_as_float((unsigned)(p0.x >> 32)) * *(const float*)(sb + (unsigned)p0.x);
                acc += __uint_as_float((unsigned)(p0.y >> 32)) * *(const float*)(sb + (unsigned)p0.y);
                acc += __uint_as_float((unsigned)(p1.x >> 32)) * *(const float*)(sb + (unsigned)p1.x);
                acc += __uint_as_float((unsigned)(p1.y >> 32)) * *(const float*)(sb + (unsigned)p1.y);
            }
            for (; j < n; ++j) {
                const u64 e0 = e[j];
                acc += __uint_as_float((unsigned)(e0 >> 32)) * *(const float*)(sb + (unsigned)e0);
            }
            accs[sg] = acc;
        }
        // first-occurrence abs-argmax (strict >) + sigmoid
        float best = accs[0];
        float ba = fabsf(best);
#pragma unroll
        for (int sg = 1; sg < NSEG; ++sg) {
            const float v = accs[sg];
            const float a = fabsf(v);
            if (a > ba) { ba = a; best = v; }
        }
        gT[(size_t)u * 256 + b0 + lane] = 1.0f / (1.0f + __expf(-best));
    }
}

// =====================================================================
// FF spMM (gate applied in kwinners): yT[r][b] = bias[r] + sum w*xT[c][b]
// One block per output row (2048 blocks); entries staged in smem (16B
// aligned), read back as LDS.128 pairs; unroll 8 for L2 MLP.
// =====================================================================
__global__ __launch_bounds__(256)
void fspmm(const float* __restrict__ xT, const u64* __restrict__ ell,
           const int* __restrict__ cnt, const float* __restrict__ bias,
           float* __restrict__ yT) {
    __shared__ alignas(16) u64 fe[FW];
    const int r = blockIdx.x;
    const int tid = threadIdx.x;
    const int n = cnt[r];
    for (int j = tid; j < n; j += 256) fe[j] = ell[(size_t)r * FW + j];
    __syncthreads();
    const char* xb = (const char*)xT + tid * 4;
    const ulonglong2* fe2 = (const ulonglong2*)fe;
    float acc = 0.f;
    int j = 0;
    for (; j + 8 <= n; j += 8) {
        float p = 0.f;
#pragma unroll
        for (int q = 0; q < 4; ++q) {
            const ulonglong2 e = fe2[(j >> 1) + q];
            p += __uint_as_float((unsigned)(e.x >> 32)) * *(const float*)(xb + (unsigned)e.x);
            p += __uint_as_float((unsigned)(e.y >> 32)) * *(const float*)(xb + (unsigned)e.y);
        }
        acc += p;
    }
    for (; j < n; ++j) {
        const u64 e = fe[j];
        acc += __uint_as_float((unsigned)(e >> 32)) * *(const float*)(xb + (unsigned)e);
    }
    yT[(size_t)r * 256 + tid] = acc + bias[r];
}

// =====================================================================
// k-winners with fused gate: val = yT[i][b] * gT[i][b]; exact top-KWIN
// via 4-pass radix select; single-warp shfl suffix scan bin selection.
// mode 0 -> transposed hT[i][b]; mode 1 -> row-major h2[b][i].
// =====================================================================
__global__ __launch_bounds__(256)
void kwinners_k(const float* __restrict__ yT, const float* __restrict__ gT,
                float* __restrict__ outT, float* __restrict__ outN, int mode) {
    __shared__ unsigned keys[HID];
    __shared__ int hist[256];
    __shared__ int s_digit;
    __shared__ int s_need;
    const int b = blockIdx.x, tid = threadIdx.x;
    for (int i = tid; i < HID; i += 256) {
        const float v = yT[(size_t)i * 256 + b] * gT[(size_t)i * 256 + b];
        unsigned u = __float_as_uint(v);
        u = (u & 0x80000000u) ? ~u : (u | 0x80000000u);  // monotonic ascending
        keys[i] = u;
    }
    if (tid == 0) s_need = KWIN;
    __syncthreads();

    unsigned prefix = 0, pmask = 0;
    for (int pass = 0; pass < 4; ++pass) {
        const int shift = 24 - 8 * pass;
        hist[tid] = 0;
        __syncthreads();
        for (int i = tid; i < HID; i += 256) {
            const unsigned u = keys[i];
            if ((u & pmask) == prefix) atomicAdd(&hist[(u >> shift) & 255], 1);
        }
        __syncthreads();
        if (tid < 32) {
            const int need = s_need;
            const int base = tid * 8;
            int gs = 0;
#pragma unroll
            for (int k = 0; k < 8; ++k) gs += hist[base + k];
            int S = gs;  // inclusive suffix sum across lanes
#pragma unroll
            for (int o = 1; o < 32; o <<= 1) {
                const int t = __shfl_down_sync(0xffffffffu, S, o);
                if (tid + o < 32) S += t;
            }
            int Snext = __shfl_down_sync(0xffffffffu, S, 1);
            if (tid == 31) Snext = 0;
            if (S >= need && Snext < need) {  // unique crossing lane
                int c = Snext;
#pragma unroll
                for (int k = 7; k >= 0; --k) {
                    const int hb = hist[base + k];
                    if (c + hb >= need) { s_digit = base + k; s_need = need - c; break; }
                    c += hb;
                }
            }
        }
        __syncthreads();
        prefix |= ((unsigned)s_digit) << shift;
        pmask |= 0xFFu << shift;
    }
    const unsigned thr = prefix;  // key of the KWIN-th largest
    for (int i = tid; i < HID; i += 256) {
        const unsigned u = keys[i];
        float val = 0.f;
        if (u >= thr) {
            const unsigned ob = (u & 0x80000000u) ? (u & 0x7FFFFFFFu) : ~u;
            val = __uint_as_float(ob);
        }
        if (mode == 0) outT[(size_t)i * 256 + b] = val;
        else           outN[(size_t)b * HID + i] = val;
    }
}

// =====================================================================
// EiDense head: out[b,o] = h.Wex[o] - (h.Wix)*Wei[o] + b_out[o]
// =====================================================================
__global__ __launch_bounds__(256)
void head_kernel(const float* __restrict__ h, const float* __restrict__ Wex,
                 const float* __restrict__ Wix, const float* __restrict__ Wei,
                 const float* __restrict__ bo, float* __restrict__ out) {
    __shared__ alignas(16) float sh[4][HID];
    __shared__ float st[4];
    const int b0 = blockIdx.x * 4;
    const int tid = threadIdx.x;
    for (int i = tid; i < 4 * HID; i += 256)
        (&sh[0][0])[i] = h[(size_t)b0 * HID + i];
    __syncthreads();
    const int wid = tid >> 5;
    const int lane = tid & 31;
    if (wid < 4) {
        float p = 0.f;
        for (int u = lane; u < HID; u += 32) p += sh[wid][u] * Wix[u];
#pragma unroll
        for (int o = 16; o; o >>= 1) p += __shfl_xor_sync(0xffffffffu, p, o);
        if (lane == 0) st[wid] = p;
    }
    __syncthreads();
    for (int o = wid; o < OUTD; o += 8) {
        float a0 = 0.f, a1 = 0.f, a2 = 0.f, a3 = 0.f;
        const float* wrow = Wex + (size_t)o * HID;
        for (int u = lane; u < HID; u += 32) {
            const float w = wrow[u];
            a0 += sh[0][u] * w;
            a1 += sh[1][u] * w;
            a2 += sh[2][u] * w;
            a3 += sh[3][u] * w;
        }
#pragma unroll
        for (int sft = 16; sft; sft >>= 1) {
            a0 += __shfl_xor_sync(0xffffffffu, a0, sft);
            a1 += __shfl_xor_sync(0xffffffffu, a1, sft);
            a2 += __shfl_xor_sync(0xffffffffu, a2, sft);
            a3 += __shfl_xor_sync(0xffffffffu, a3, sft);
        }
        if (lane == 0) {
            const float we = Wei[o];
            const float bb = bo[o];
            out[(size_t)(b0 + 0) * OUTD + o] = a0 - st[0] * we + bb;
            out[(size_t)(b0 + 1) * OUTD + o] = a1 - st[1] * we + bb;
            out[(size_t)(b0 + 2) * OUTD + o] = a2 - st[2] * we + bb;
            out[(size_t)(b0 + 3) * OUTD + o] = a3 - st[3] * we + bb;
        }
    }
}

// =====================================================================
// launch — dspmm_gate2 kept at user-launch #4 (ncu -s 5 slot)
// =====================================================================
extern "C" void kernel_launch(void* const* d_in, const int* in_sizes, int n_in,
                              void* d_out, int out_size) {
    const float* x      = (const float*)d_in[0];
    const float* ctx    = (const float*)d_in[1];
    const float* W1     = (const float*)d_in[2];
    const float* b1     = (const float*)d_in[3];
    const float* segW1  = (const float*)d_in[4];
    const float* maskW1 = (const float*)d_in[5];
    const float* maskS1 = (const float*)d_in[6];
    const float* W2     = (const float*)d_in[7];
    const float* b2     = (const float*)d_in[8];
    const float* segW2  = (const float*)d_in[9];
    const float* maskW2 = (const float*)d_in[10];
    const float* maskS2 = (const float*)d_in[11];
    const float* Wex    = (const float*)d_in[12];
    const float* Wix    = (const float*)d_in[13];
    const float* Wei    = (const float*)d_in[14];
    const float* bo     = (const float*)d_in[15];
    float* out = (float*)d_out;

    float *ctxT, *xT, *hT, *yT, *gT1, *gT2, *h2;
    u64 *ellF1, *ellF2;
    int *cntF1, *cntF2;
    cudaGetSymbolAddress((void**)&ctxT,  g_ctxT);
    cudaGetSymbolAddress((void**)&xT,    g_xT);
    cudaGetSymbolAddress((void**)&hT,    g_hT);
    cudaGetSymbolAddress((void**)&yT,    g_yT);
    cudaGetSymbolAddress((void**)&gT1,   g_gT1);
    cudaGetSymbolAddress((void**)&gT2,   g_gT2);
    cudaGetSymbolAddress((void**)&h2,    g_h2);
    cudaGetSymbolAddress((void**)&ellF1, g_ellF1);
    cudaGetSymbolAddress((void**)&ellF2, g_ellF2);
    cudaGetSymbolAddress((void**)&cntF1, g_cntF1);
    cudaGetSymbolAddress((void**)&cntF2, g_cntF2);

    const int dsmem = DCTX * 32 * 4;  // 128 KB
    cudaFuncSetAttribute(dspmm_gate2, cudaFuncAttributeMaxDynamicSharedMemorySize, dsmem);

    // (1) all four ELL builds fused (ballot-scan)
    prep_build<<<5632, 256>>>(segW1, maskS1, segW2, maskS2,
                              W1, maskW1, W2, maskW2);
    // (2) both transposes
    prep_transpose<<<768, 256>>>(ctx, x);
    // (3) layer 1 FF (independent of dendrite path)
    fspmm<<<HID, 256>>>(xT, ellF1, cntF1, b1, yT);
    // (4) both layers' dendrite gates  <-- ncu-profiled slot
    dspmm_gate2<<<256, 1024, dsmem>>>(ctxT);
    // (5) layer 1 k-winners (applies gate 1) -> hT
    kwinners_k<<<BDIM, 256>>>(yT, gT1, hT, h2, 0);
    // (6) layer 2 FF
    fspmm<<<HID, 256>>>(hT, ellF2, cntF2, b2, yT);
    // (7) layer 2 k-winners (applies gate 2) -> h2 row-major
    kwinners_k<<<BDIM, 256>>>(yT, gT2, hT, h2, 1);
    // (8) EiDense head
    head_kernel<<<BDIM / 4, 256>>>(h2, Wex, Wix, Wei, bo, out);
}

// round 13
// speedup vs baseline: 1.1937x; 1.1937x over previous
#include <cuda_runtime.h>
#include <cstdint>
#include <math.h>

// ---------------- problem constants ----------------
#define BDIM 256
#define DIN 2048
#define HID 2048
#define DCTX 1024
#define NSEG 10
#define NR (HID * NSEG) /* 20480 */
#define OUTD 100
#define KWIN 102

#define DW 128    // ELL row width for dendrite rows (mean nz 51.2)
#define FW 192    // ELL width for FF rows (mean nz 102.4)

typedef unsigned long long u64;

// ---------------- scratch (no allocations allowed) ----------------
__device__ float g_ctxT[DCTX * BDIM];       // 1 MB  context transposed [c][b]
__device__ float g_xT[DIN * BDIM];          // 2 MB  x transposed [c][b]
__device__ float g_hT[HID * BDIM];          // 2 MB  layer-1 winners transposed [c][b]
__device__ float g_yT[HID * BDIM];          // 2 MB  ff pre-activation [n][b]
__device__ float g_gT1[HID * BDIM];         // 2 MB  dendrite gate layer 1 [u][b]
__device__ float g_gT2[HID * BDIM];         // 2 MB  dendrite gate layer 2 [u][b]
__device__ float g_h2[BDIM * HID];          // 2 MB  layer-2 winners, row-major
__device__ __align__(16) u64 g_ellD1[(size_t)NR * DW];   // 21 MB ELL (dendrite L1)
__device__ __align__(16) u64 g_ellD2[(size_t)NR * DW];   // 21 MB ELL (dendrite L2)
__device__ int  g_cntD1[NR];
__device__ int  g_cntD2[NR];
__device__ int  g_cntDLo1[NR];   // entries with col < 512 (c-split point)
__device__ int  g_cntDLo2[NR];
__device__ __align__(16) u64 g_ellF1[(size_t)HID * FW];  // 3 MB  ELL (ff L1)
__device__ __align__(16) u64 g_ellF2[(size_t)HID * FW];  // 3 MB  ELL (ff L2)
__device__ int  g_cntF1[HID];
__device__ int  g_cntF2[HID];

// =====================================================================
// warp-per-row ELL compaction: ballot+popc positioning (R12-proven).
// Lane-major ascending column order. entry = (f32 bits << 32)|(col*mult).
// loChunkEnd>0: also record count of entries in chunks [0,loChunkEnd)
// (i.e. col < loChunkEnd*128) into cntLo.
// =====================================================================
__device__ __forceinline__
void build_row(const float* __restrict__ W, const float* __restrict__ M,
               u64* __restrict__ ell, int* __restrict__ cnt,
               int* __restrict__ cntLo, int loChunkEnd,
               int K, int width, int mult, int row, int lane) {
    const float4* wr = (const float4*)(W + (size_t)row * K);
    const float4* mr = (const float4*)(M + (size_t)row * K);
    u64* er = ell + (size_t)row * width;
    const int chunks = K >> 7;  // 128 floats per chunk (float4 per lane)
    const unsigned below = (1u << lane) - 1u;
    int base = 0, baseLo = 0;
    float4 w = wr[lane];
    float4 m = mr[lane];
    for (int c = 0; c < chunks; ++c) {
        float4 wn, mn;
        if (c + 1 < chunks) {
            wn = wr[(c + 1) * 32 + lane];
            mn = mr[(c + 1) * 32 + lane];
        }
        const unsigned bx = __ballot_sync(0xffffffffu, m.x != 0.f);
        const unsigned by = __ballot_sync(0xffffffffu, m.y != 0.f);
        const unsigned bz = __ballot_sync(0xffffffffu, m.z != 0.f);
        const unsigned bw = __ballot_sync(0xffffffffu, m.w != 0.f);
        int p = base + __popc(bx & below) + __popc(by & below)
                     + __popc(bz & below) + __popc(bw & below);
        const int col0 = c * 128 + lane * 4;
        if (m.x != 0.f && p < width) er[p++] = ((u64)__float_as_uint(w.x) << 32) | (unsigned)((col0 + 0) * mult);
        if (m.y != 0.f && p < width) er[p++] = ((u64)__float_as_uint(w.y) << 32) | (unsigned)((col0 + 1) * mult);
        if (m.z != 0.f && p < width) er[p++] = ((u64)__float_as_uint(w.z) << 32) | (unsigned)((col0 + 2) * mult);
        if (m.w != 0.f && p < width) er[p++] = ((u64)__float_as_uint(w.w) << 32) | (unsigned)((col0 + 3) * mult);
        base += __popc(bx) + __popc(by) + __popc(bz) + __popc(bw);
        if (c == loChunkEnd - 1) baseLo = base;
        w = wn; m = mn;
    }
    if (lane == 0) {
        cnt[row] = base < width ? base : width;
        if (cntLo) cntLo[row] = baseLo < width ? baseLo : width;
    }
}

// =====================================================================
// K1a: fused builds only.
// Dendrite entries: mult=256 (64-batch float2 tile), cntLo at col=512.
// FF entries: mult=1024 (256-batch float tile), no cntLo.
// Block ranges:
//   [0,2560)      build dendrite L1   (8 rows/block)
//   [2560,5120)   build dendrite L2
//   [5120,5376)   build FF L1
//   [5376,5632)   build FF L2
// =====================================================================
__global__ __launch_bounds__(256)
void prep_build(const float* __restrict__ segW1, const float* __restrict__ maskS1,
                const float* __restrict__ segW2, const float* __restrict__ maskS2,
                const float* __restrict__ W1, const float* __restrict__ maskW1,
                const float* __restrict__ W2, const float* __restrict__ maskW2) {
    const int bid = blockIdx.x;
    const int tid = threadIdx.x;
    const int lane = tid & 31;
    const int wid = tid >> 5;

    if (bid < 5120) {  // dendrite builds
        const int part = bid / 2560;                 // 0 or 1
        const int row = (bid % 2560) * 8 + wid;      // 0..20479
        if (part == 0) build_row(segW1, maskS1, g_ellD1, g_cntD1, g_cntDLo1, 4, DCTX, DW, 256, row, lane);
        else           build_row(segW2, maskS2, g_ellD2, g_cntD2, g_cntDLo2, 4, DCTX, DW, 256, row, lane);
        return;
    }
    // FF builds
    const int part = (bid - 5120) >> 8;              // 0 or 1 (256 blocks each)
    const int row = ((bid - 5120) & 255) * 8 + wid;
    if (part == 0) build_row(W1, maskW1, g_ellF1, g_cntF1, (int*)0, -1, DIN, FW, 1024, row, lane);
    else           build_row(W2, maskW2, g_ellF2, g_cntF2, (int*)0, -1, HID, FW, 1024, row, lane);
}

// =====================================================================
// K1b: both transposes. Block ranges: [0,256) ctx, [256,768) x.
// in[R=256][C] -> out[C][256]
// =====================================================================
__global__ __launch_bounds__(256)
void prep_transpose(const float* __restrict__ ctx, const float* __restrict__ x) {
    __shared__ float t[32][33];
    const int bid = blockIdx.x;
    const int tid = threadIdx.x;
    const float* in;
    float* outp;
    int C, lb;
    if (bid < 256) { in = ctx; outp = g_ctxT; C = DCTX; lb = bid; }
    else           { in = x;   outp = g_xT;   C = DIN;  lb = bid - 256; }
    const int nbx = C >> 5;
    const int c0 = (lb % nbx) * 32;
    const int r0 = (lb / nbx) * 32;
    const int xx = tid & 31, yy = tid >> 5;
#pragma unroll
    for (int i = 0; i < 32; i += 8)
        t[yy + i][xx] = in[(size_t)(r0 + yy + i) * C + c0 + xx];
    __syncthreads();
#pragma unroll
    for (int i = 0; i < 32; i += 8)
        outp[(size_t)(c0 + yy + i) * BDIM + r0 + xx] = t[xx][yy + i];
}

// =====================================================================
// K2: fused dendrite spMM + gate, 64-batch c-split version.
// Block = 1024 thr (32 warps); warp = 1 unit; lane = 2 batches (float2).
// smem tile = ctx[c-half 512][64 batches] = 128 KB, swapped between the
// two passes; entries split at cntLo (col<512 vs col>=512).
// Per entry: 1 broadcast LDG.64 + 2 LDS wavefronts per 64 batches
// (was 2 wf per 32) -> ~25% fewer L1 wavefronts.
// grid 512: [layer(2)][bg(4)][ub(64)].   <-- PROFILED (user slot 4)
// =====================================================================
__global__ __launch_bounds__(1024, 1)
void dspmm_gate2(const float* __restrict__ ctxT) {
    extern __shared__ float s[];  // 512 * 64 floats = 128 KB
    const int id = blockIdx.x;
    const int layer = id >> 8;
    const int bg = (id >> 6) & 3;
    const int ub = id & 63;
    const u64* __restrict__ ell = layer ? g_ellD2 : g_ellD1;
    const int* __restrict__ cnt = layer ? g_cntD2 : g_cntD1;
    const int* __restrict__ cntLo = layer ? g_cntDLo2 : g_cntDLo1;
    float* __restrict__ gT = layer ? g_gT2 : g_gT1;

    const int b0 = bg * 64;
    const int tid = threadIdx.x;
    const int wid = tid >> 5, lane = tid & 31;
    const char* sb = (const char*)s + lane * 8;
    const int u = ub * 32 + wid;
    const int r0 = u * NSEG;
    const int cn = (lane < NSEG) ? cnt[r0 + lane] : 0;
    const int cl = (lane < NSEG) ? cntLo[r0 + lane] : 0;

    float2 accs[NSEG];
#pragma unroll
    for (int sg = 0; sg < NSEG; ++sg) accs[sg] = make_float2(0.f, 0.f);

#pragma unroll
    for (int pass = 0; pass < 2; ++pass) {
        if (pass) __syncthreads();  // all warps done reading previous tile
        // stage ctx[pass*512 .. +512)[b0 .. b0+63]
        for (int i = tid; i < 512 * 16; i += 1024) {
            const int c = i >> 4, q = (i & 15) * 4;
            *(float4*)&s[c * 64 + q] =
                *(const float4*)&ctxT[(size_t)(pass * 512 + c) * 256 + b0 + q];
        }
        __syncthreads();
        const unsigned off = pass ? 131072u : 0u;  // 512*256 byte rebase
#pragma unroll
        for (int sg = 0; sg < NSEG; ++sg) {
            const int j0 = pass ? __shfl_sync(0xffffffffu, cl, sg) : 0;
            const int j1 = pass ? __shfl_sync(0xffffffffu, cn, sg)
                                : __shfl_sync(0xffffffffu, cl, sg);
            const u64* e = ell + (size_t)(r0 + sg) * DW;
            float ax = accs[sg].x, ay = accs[sg].y;
            int j = j0;
            for (; j + 2 <= j1; j += 2) {
                const u64 e0 = e[j], e1 = e[j + 1];
                const float w0 = __uint_as_float((unsigned)(e0 >> 32));
                const float w1 = __uint_as_float((unsigned)(e1 >> 32));
                const float2 v0 = *(const float2*)(sb + ((unsigned)e0 - off));
                const float2 v1 = *(const float2*)(sb + ((unsigned)e1 - off));
                ax += w0 * v0.x; ay += w0 * v0.y;
                ax += w1 * v1.x; ay += w1 * v1.y;
            }
            if (j < j1) {
                const u64 e0 = e[j];
                const float w0 = __uint_as_float((unsigned)(e0 >> 32));
                const float2 v0 = *(const float2*)(sb + ((unsigned)e0 - off));
                ax += w0 * v0.x; ay += w0 * v0.y;
            }
            accs[sg].x = ax; accs[sg].y = ay;
        }
    }
    // first-occurrence abs-argmax (strict >) + sigmoid, per batch component
    float bxv = accs[0].x, byv = accs[0].y;
    float bax = fabsf(bxv), bay = fabsf(byv);
#pragma unroll
    for (int sg = 1; sg < NSEG; ++sg) {
        const float vx = accs[sg].x, vy = accs[sg].y;
        const float axv = fabsf(vx), ayv = fabsf(vy);
        if (axv > bax) { bax = axv; bxv = vx; }
        if (ayv > bay) { bay = ayv; byv = vy; }
    }
    const float2 g = make_float2(1.0f / (1.0f + __expf(-bxv)),
                                 1.0f / (1.0f + __expf(-byv)));
    *(float2*)&gT[(size_t)u * 256 + b0 + lane * 2] = g;
}

// =====================================================================
// FF spMM (gate applied in kwinners): yT[r][b] = bias[r] + sum w*xT[c][b]
// One block per output row (2048 blocks); entries staged in smem (16B
// aligned), read back as LDS.128 pairs; unroll 8 for L2 MLP.
// =====================================================================
__global__ __launch_bounds__(256)
void fspmm(const float* __restrict__ xT, const u64* __restrict__ ell,
           const int* __restrict__ cnt, const float* __restrict__ bias,
           float* __restrict__ yT) {
    __shared__ alignas(16) u64 fe[FW];
    const int r = blockIdx.x;
    const int tid = threadIdx.x;
    const int n = cnt[r];
    for (int j = tid; j < n; j += 256) fe[j] = ell[(size_t)r * FW + j];
    __syncthreads();
    const char* xb = (const char*)xT + tid * 4;
    const ulonglong2* fe2 = (const ulonglong2*)fe;
    float acc = 0.f;
    int j = 0;
    for (; j + 8 <= n; j += 8) {
        float p = 0.f;
#pragma unroll
        for (int q = 0; q < 4; ++q) {
            const ulonglong2 e = fe2[(j >> 1) + q];
            p += __uint_as_float((unsigned)(e.x >> 32)) * *(const float*)(xb + (unsigned)e.x);
            p += __uint_as_float((unsigned)(e.y >> 32)) * *(const float*)(xb + (unsigned)e.y);
        }
        acc += p;
    }
    for (; j < n; ++j) {
        const u64 e = fe[j];
        acc += __uint_as_float((unsigned)(e >> 32)) * *(const float*)(xb + (unsigned)e);
    }
    yT[(size_t)r * 256 + tid] = acc + bias[r];
}

// =====================================================================
// k-winners with fused gate: val = yT[i][b] * gT[i][b]; exact top-KWIN
// via 4-pass radix select; single-warp shfl suffix scan bin selection.
// mode 0 -> transposed hT[i][b]; mode 1 -> row-major h2[b][i].
// =====================================================================
__global__ __launch_bounds__(256)
void kwinners_k(const float* __restrict__ yT, const float* __restrict__ gT,
                float* __restrict__ outT, float* __restrict__ outN, int mode) {
    __shared__ unsigned keys[HID];
    __shared__ int hist[256];
    __shared__ int s_digit;
    __shared__ int s_need;
    const int b = blockIdx.x, tid = threadIdx.x;
    for (int i = tid; i < HID; i += 256) {
        const float v = yT[(size_t)i * 256 + b] * gT[(size_t)i * 256 + b];
        unsigned u = __float_as_uint(v);
        u = (u & 0x80000000u) ? ~u : (u | 0x80000000u);  // monotonic ascending
        keys[i] = u;
    }
    if (tid == 0) s_need = KWIN;
    __syncthreads();

    unsigned prefix = 0, pmask = 0;
    for (int pass = 0; pass < 4; ++pass) {
        const int shift = 24 - 8 * pass;
        hist[tid] = 0;
        __syncthreads();
        for (int i = tid; i < HID; i += 256) {
            const unsigned u = keys[i];
            if ((u & pmask) == prefix) atomicAdd(&hist[(u >> shift) & 255], 1);
        }
        __syncthreads();
        if (tid < 32) {
            const int need = s_need;
            const int base = tid * 8;
            int gs = 0;
#pragma unroll
            for (int k = 0; k < 8; ++k) gs += hist[base + k];
            int S = gs;  // inclusive suffix sum across lanes
#pragma unroll
            for (int o = 1; o < 32; o <<= 1) {
                const int t = __shfl_down_sync(0xffffffffu, S, o);
                if (tid + o < 32) S += t;
            }
            int Snext = __shfl_down_sync(0xffffffffu, S, 1);
            if (tid == 31) Snext = 0;
            if (S >= need && Snext < need) {  // unique crossing lane
                int c = Snext;
#pragma unroll
                for (int k = 7; k >= 0; --k) {
                    const int hb = hist[base + k];
                    if (c + hb >= need) { s_digit = base + k; s_need = need - c; break; }
                    c += hb;
                }
            }
        }
        __syncthreads();
        prefix |= ((unsigned)s_digit) << shift;
        pmask |= 0xFFu << shift;
    }
    const unsigned thr = prefix;  // key of the KWIN-th largest
    for (int i = tid; i < HID; i += 256) {
        const unsigned u = keys[i];
        float val = 0.f;
        if (u >= thr) {
            const unsigned ob = (u & 0x80000000u) ? (u & 0x7FFFFFFFu) : ~u;
            val = __uint_as_float(ob);
        }
        if (mode == 0) outT[(size_t)i * 256 + b] = val;
        else           outN[(size_t)b * HID + i] = val;
    }
}

// =====================================================================
// EiDense head: out[b,o] = h.Wex[o] - (h.Wix)*Wei[o] + b_out[o]
// =====================================================================
__global__ __launch_bounds__(256)
void head_kernel(const float* __restrict__ h, const float* __restrict__ Wex,
                 const float* __restrict__ Wix, const float* __restrict__ Wei,
                 const float* __restrict__ bo, float* __restrict__ out) {
    __shared__ alignas(16) float sh[4][HID];
    __shared__ float st[4];
    const int b0 = blockIdx.x * 4;
    const int tid = threadIdx.x;
    for (int i = tid; i < 4 * HID; i += 256)
        (&sh[0][0])[i] = h[(size_t)b0 * HID + i];
    __syncthreads();
    const int wid = tid >> 5;
    const int lane = tid & 31;
    if (wid < 4) {
        float p = 0.f;
        for (int u = lane; u < HID; u += 32) p += sh[wid][u] * Wix[u];
#pragma unroll
        for (int o = 16; o; o >>= 1) p += __shfl_xor_sync(0xffffffffu, p, o);
        if (lane == 0) st[wid] = p;
    }
    __syncthreads();
    for (int o = wid; o < OUTD; o += 8) {
        float a0 = 0.f, a1 = 0.f, a2 = 0.f, a3 = 0.f;
        const float* wrow = Wex + (size_t)o * HID;
        for (int u = lane; u < HID; u += 32) {
            const float w = wrow[u];
            a0 += sh[0][u] * w;
            a1 += sh[1][u] * w;
            a2 += sh[2][u] * w;
            a3 += sh[3][u] * w;
        }
#pragma unroll
        for (int sft = 16; sft; sft >>= 1) {
            a0 += __shfl_xor_sync(0xffffffffu, a0, sft);
            a1 += __shfl_xor_sync(0xffffffffu, a1, sft);
            a2 += __shfl_xor_sync(0xffffffffu, a2, sft);
            a3 += __shfl_xor_sync(0xffffffffu, a3, sft);
        }
        if (lane == 0) {
            const float we = Wei[o];
            const float bb = bo[o];
            out[(size_t)(b0 + 0) * OUTD + o] = a0 - st[0] * we + bb;
            out[(size_t)(b0 + 1) * OUTD + o] = a1 - st[1] * we + bb;
            out[(size_t)(b0 + 2) * OUTD + o] = a2 - st[2] * we + bb;
            out[(size_t)(b0 + 3) * OUTD + o] = a3 - st[3] * we + bb;
        }
    }
}

// =====================================================================
// launch — dspmm_gate2 kept at user-launch #4 (ncu -s 5 slot)
// =====================================================================
extern "C" void kernel_launch(void* const* d_in, const int* in_sizes, int n_in,
                              void* d_out, int out_size) {
    const float* x      = (const float*)d_in[0];
    const float* ctx    = (const float*)d_in[1];
    const float* W1     = (const float*)d_in[2];
    const float* b1     = (const float*)d_in[3];
    const float* segW1  = (const float*)d_in[4];
    const float* maskW1 = (const float*)d_in[5];
    const float* maskS1 = (const float*)d_in[6];
    const float* W2     = (const float*)d_in[7];
    const float* b2     = (const float*)d_in[8];
    const float* segW2  = (const float*)d_in[9];
    const float* maskW2 = (const float*)d_in[10];
    const float* maskS2 = (const float*)d_in[11];
    const float* Wex    = (const float*)d_in[12];
    const float* Wix    = (const float*)d_in[13];
    const float* Wei    = (const float*)d_in[14];
    const float* bo     = (const float*)d_in[15];
    float* out = (float*)d_out;

    float *ctxT, *xT, *hT, *yT, *gT1, *gT2, *h2;
    u64 *ellF1, *ellF2;
    int *cntF1, *cntF2;
    cudaGetSymbolAddress((void**)&ctxT,  g_ctxT);
    cudaGetSymbolAddress((void**)&xT,    g_xT);
    cudaGetSymbolAddress((void**)&hT,    g_hT);
    cudaGetSymbolAddress((void**)&yT,    g_yT);
    cudaGetSymbolAddress((void**)&gT1,   g_gT1);
    cudaGetSymbolAddress((void**)&gT2,   g_gT2);
    cudaGetSymbolAddress((void**)&h2,    g_h2);
    cudaGetSymbolAddress((void**)&ellF1, g_ellF1);
    cudaGetSymbolAddress((void**)&ellF2, g_ellF2);
    cudaGetSymbolAddress((void**)&cntF1, g_cntF1);
    cudaGetSymbolAddress((void**)&cntF2, g_cntF2);

    const int dsmem = 512 * 64 * 4;  // 128 KB
    cudaFuncSetAttribute(dspmm_gate2, cudaFuncAttributeMaxDynamicSharedMemorySize, dsmem);

    // (1) all four ELL builds fused (ballot-scan, +cntLo for dendrites)
    prep_build<<<5632, 256>>>(segW1, maskS1, segW2, maskS2,
                              W1, maskW1, W2, maskW2);
    // (2) both transposes
    prep_transpose<<<768, 256>>>(ctx, x);
    // (3) layer 1 FF (independent of dendrite path)
    fspmm<<<HID, 256>>>(xT, ellF1, cntF1, b1, yT);
    // (4) both layers' dendrite gates, 64-batch c-split  <-- ncu slot
    dspmm_gate2<<<512, 1024, dsmem>>>(ctxT);
    // (5) layer 1 k-winners (applies gate 1) -> hT
    kwinners_k<<<BDIM, 256>>>(yT, gT1, hT, h2, 0);
    // (6) layer 2 FF
    fspmm<<<HID, 256>>>(hT, ellF2, cntF2, b2, yT);
    // (7) layer 2 k-winners (applies gate 2) -> h2 row-major
    kwinners_k<<<BDIM, 256>>>(yT, gT2, hT, h2, 1);
    // (8) EiDense head
    head_kernel<<<BDIM / 4, 256>>>(h2, Wex, Wix, Wei, bo, out);
}